// round 6
// baseline (speedup 1.0000x reference)
#include <cuda_runtime.h>
#include <cstdint>

#define THREADS 256
#define ROWS    512   // rows per block (2 per thread in compute phase)
#define NDIM    6
#define JLEV    8
#define CHAN    64

// ---------------------------------------------------------------------------
// One block handles ROWS consecutive rows:
//  phase 1: stage z chunk in SMEM (float4-coalesced), compute packed big_index
//           (2 rows per thread)
//  phase 2: cooperative codebook gather, MLP-4 pipelined, 128KB contiguous
//           coalesced store burst per block
// ---------------------------------------------------------------------------
__global__ __launch_bounds__(THREADS)
void fsq_quantize_kernel(const float* __restrict__ z,
                         const float* __restrict__ perc,
                         const float* __restrict__ cb,
                         float* __restrict__ out_q,      // [B,64]
                         float* __restrict__ out_idx_f,  // [B] float tail
                         int B)
{
    __shared__ float sz[ROWS * NDIM];     // 12 KB
    __shared__ float sp[JLEV * NDIM];     // 192 B
    __shared__ int   sidx[ROWS];          // 2 KB

    const int tid = threadIdx.x;
    const long long base = (long long)blockIdx.x * ROWS;
    const bool full = (base + ROWS) <= (long long)B;
    const int nrows = full ? ROWS : (int)((long long)B - base);
    if (nrows <= 0) return;

    if (tid < JLEV * NDIM) sp[tid] = perc[tid];

    if (full) {
        // 3072 floats = 768 float4; block offset 12288B -> 16B aligned
        float4* szv = (float4*)sz;
        const float4* zv = (const float4*)(z + base * NDIM);
        szv[tid]           = __ldcs(&zv[tid]);
        szv[256 + tid]     = __ldcs(&zv[256 + tid]);
        szv[512 + tid]     = __ldcs(&zv[512 + tid]);
    } else {
        const int total = nrows * NDIM;
        for (int e = tid; e < total; e += THREADS)
            sz[e] = __ldcs(&z[base * NDIM + e]);
    }
    __syncthreads();

    #pragma unroll
    for (int rr = 0; rr < 2; rr++) {
        const int r = tid + rr * THREADS;
        if (r < nrows) {
            int big = 0;
            #pragma unroll
            for (int i = 0; i < NDIM; i++) {
                const float v = sz[r * NDIM + i];
                int idx = 0;
                // sorted per-dim edges: max{ j : v >= p[j] } == count over j>=1
                #pragma unroll
                for (int j = 1; j < JLEV; j++)
                    idx += (v >= sp[j * NDIM + i]) ? 1 : 0;
                big |= idx << (3 * i);   // basis = 8^i
            }
            sidx[r] = big;
            if (out_idx_f) out_idx_f[base + r] = (float)big;
        }
    }
    __syncthreads();

    if (!out_q) return;

    if (full) {
        // 16 lanes x float4 per row. 8192 float4 per block; each thread does
        // 32 vectors in 8 batches of 4 independent loads (explicit MLP=4).
        // __ldcg: 64MB codebook never fits L1 -> skip L1 allocation.
        float4* dstb = (float4*)(out_q + base * (long long)CHAN);
        #pragma unroll
        for (int u0 = 0; u0 < 32; u0 += 4) {
            const float4* s[4];
            #pragma unroll
            for (int k = 0; k < 4; k++) {
                const int e = (u0 + k) * THREADS + tid;
                s[k] = (const float4*)(cb + (long long)sidx[e >> 4] * CHAN)
                       + (e & 15);
            }
            float4 v0 = __ldcg(s[0]);
            float4 v1 = __ldcg(s[1]);
            float4 v2 = __ldcg(s[2]);
            float4 v3 = __ldcg(s[3]);
            __stcs(&dstb[(u0 + 0) * THREADS + tid], v0);
            __stcs(&dstb[(u0 + 1) * THREADS + tid], v1);
            __stcs(&dstb[(u0 + 2) * THREADS + tid], v2);
            __stcs(&dstb[(u0 + 3) * THREADS + tid], v3);
        }
    } else {
        const int totalv = nrows * (CHAN / 4);
        for (int e = tid; e < totalv; e += THREADS) {
            const int r = e >> 4;
            const int c = e & 15;
            const float4 v =
                __ldcg((const float4*)(cb + (long long)sidx[r] * CHAN) + c);
            __stcs((float4*)(out_q + (base + r) * (long long)CHAN) + c, v);
        }
    }
}

extern "C" void kernel_launch(void* const* d_in, const int* in_sizes, int n_in,
                              void* d_out, int out_size)
{
    const float* z    = (const float*)d_in[0];   // [B,6]
    const float* perc = (const float*)d_in[1];   // [8,6]
    const float* cb   = (const float*)d_in[2];   // [262144,64]
    const int B = in_sizes[0] / NDIM;

    const long long nq = (long long)B * CHAN;

    float* out_q     = (float*)d_out;
    float* out_idx_f = nullptr;
    if ((long long)out_size == nq + B)
        out_idx_f = (float*)d_out + nq;   // confirmed layout: [B*64 | B]

    const int blocks = (B + ROWS - 1) / ROWS;
    fsq_quantize_kernel<<<blocks, THREADS>>>(z, perc, cb, out_q, out_idx_f, B);
}

// round 7
// speedup vs baseline: 1.0068x; 1.0068x over previous
#include <cuda_runtime.h>
#include <cstdint>

#define THREADS 256
#define ROWS    256   // rows per block
#define NDIM    6
#define JLEV    8
#define CHAN    64

// ---------------------------------------------------------------------------
// One block handles ROWS consecutive rows:
//  phase 1: stage z chunk in SMEM (float4-coalesced), compute packed big_index
//  phase 2: cooperative codebook gather, double-buffered MLP-4 pipeline so
//           L2-hit load latency never gates store issue. The kernel is
//           LTS-capped (~6300 B/cyc chip-wide); goal is max sustained LSU
//           pressure at natural clock.
// ---------------------------------------------------------------------------
__global__ __launch_bounds__(THREADS, 5)
void fsq_quantize_kernel(const float* __restrict__ z,
                         const float* __restrict__ perc,
                         const float* __restrict__ cb,
                         float* __restrict__ out_q,      // [B,64]
                         float* __restrict__ out_idx_f,  // [B] float tail
                         int B)
{
    __shared__ float sz[ROWS * NDIM];     // 6 KB
    __shared__ float sp[JLEV * NDIM];     // 192 B
    __shared__ int   sidx[ROWS];          // 1 KB

    const int tid = threadIdx.x;
    const long long base = (long long)blockIdx.x * ROWS;
    const bool full = (base + ROWS) <= (long long)B;
    const int nrows = full ? ROWS : (int)((long long)B - base);
    if (nrows <= 0) return;

    if (tid < JLEV * NDIM) sp[tid] = perc[tid];

    if (full) {
        // 1536 floats = 384 float4; block offset 6144B -> 16B aligned
        float4* szv = (float4*)sz;
        const float4* zv = (const float4*)(z + base * NDIM);
        szv[tid] = __ldcs(&zv[tid]);
        if (tid < 128) szv[256 + tid] = __ldcs(&zv[256 + tid]);
    } else {
        const int total = nrows * NDIM;
        for (int e = tid; e < total; e += THREADS)
            sz[e] = __ldcs(&z[base * NDIM + e]);
    }
    __syncthreads();

    if (tid < nrows) {
        int big = 0;
        #pragma unroll
        for (int i = 0; i < NDIM; i++) {
            const float v = sz[tid * NDIM + i];
            int idx = 0;
            // sorted per-dim edges: max{ j : v >= p[j] } == count over j>=1
            #pragma unroll
            for (int j = 1; j < JLEV; j++)
                idx += (v >= sp[j * NDIM + i]) ? 1 : 0;
            big |= idx << (3 * i);   // basis = 8^i
        }
        sidx[tid] = big;
        out_idx_f[base + tid] = (float)big;
    }
    __syncthreads();

    if (full) {
        // 16 lanes x float4 per row; 4096 float4 per block; 16 vectors per
        // thread as 4 batches of 4, double-buffered: loads of batch k+1 are
        // issued before stores of batch k, so stores never wait on fresh
        // load latency. __ldcg: 64MB codebook never fits L1.
        float4* dstb = (float4*)(out_q + base * (long long)CHAN);

        float4 cur[4];
        #pragma unroll
        for (int k = 0; k < 4; k++) {
            const int e = k * THREADS + tid;
            cur[k] = __ldcg((const float4*)(cb + (long long)sidx[e >> 4] * CHAN)
                            + (e & 15));
        }

        #pragma unroll
        for (int u0 = 0; u0 < 16; u0 += 4) {
            float4 nxt[4];
            if (u0 + 4 < 16) {
                #pragma unroll
                for (int k = 0; k < 4; k++) {
                    const int e = (u0 + 4 + k) * THREADS + tid;
                    nxt[k] = __ldcg(
                        (const float4*)(cb + (long long)sidx[e >> 4] * CHAN)
                        + (e & 15));
                }
            }
            #pragma unroll
            for (int k = 0; k < 4; k++)
                __stcs(&dstb[(u0 + k) * THREADS + tid], cur[k]);
            #pragma unroll
            for (int k = 0; k < 4; k++) cur[k] = nxt[k];
        }
    } else {
        const int totalv = nrows * (CHAN / 4);
        for (int e = tid; e < totalv; e += THREADS) {
            const int r = e >> 4;
            const int c = e & 15;
            const float4 v =
                __ldcg((const float4*)(cb + (long long)sidx[r] * CHAN) + c);
            __stcs((float4*)(out_q + (base + r) * (long long)CHAN) + c, v);
        }
    }
}

extern "C" void kernel_launch(void* const* d_in, const int* in_sizes, int n_in,
                              void* d_out, int out_size)
{
    const float* z    = (const float*)d_in[0];   // [B,6]
    const float* perc = (const float*)d_in[1];   // [8,6]
    const float* cb   = (const float*)d_in[2];   // [262144,64]
    const int B = in_sizes[0] / NDIM;

    const long long nq = (long long)B * CHAN;

    float* out_q     = (float*)d_out;
    float* out_idx_f = (float*)d_out + nq;   // confirmed layout: [B*64 | B]
    (void)out_size;

    const int blocks = (B + ROWS - 1) / ROWS;
    fsq_quantize_kernel<<<blocks, THREADS>>>(z, perc, cb, out_q, out_idx_f, B);
}

// round 9
// speedup vs baseline: 1.0136x; 1.0068x over previous
#include <cuda_runtime.h>
#include <cstdint>

#define THREADS 256
#define ROWS    256   // rows per block
#define NDIM    6
#define JLEV    8
#define CHAN    64

// ---------------------------------------------------------------------------
// LTS-capped kernel (~6300 B/cyc chip-wide L2 ceiling):
//   per-launch L2 traffic = 512MB cb-read + 512MB write + 64MB misc ~= 1.09GB
//   -> ~93us floor at NAT clock. This config (R5) measured best; keep it.
//  phase 1: stage z chunk in SMEM (float4-coalesced), compute packed big_index
//  phase 2: cooperative codebook gather, MLP-4 batches, 256B coalesced rows
// ---------------------------------------------------------------------------
__global__ __launch_bounds__(THREADS)
void fsq_quantize_kernel(const float* __restrict__ z,
                         const float* __restrict__ perc,
                         const float* __restrict__ cb,
                         float* __restrict__ out_q,      // [B,64]
                         float* __restrict__ out_idx_f,  // [B] float tail
                         int B)
{
    __shared__ float sz[ROWS * NDIM];     // 6 KB
    __shared__ float sp[JLEV * NDIM];     // 192 B
    __shared__ long long soff[ROWS];      // 2 KB: precomputed float-offsets

    const int tid = threadIdx.x;
    const long long base = (long long)blockIdx.x * ROWS;
    const bool full = (base + ROWS) <= (long long)B;
    const int nrows = full ? ROWS : (int)((long long)B - base);
    if (nrows <= 0) return;

    if (tid < JLEV * NDIM) sp[tid] = perc[tid];

    if (full) {
        // 1536 floats = 384 float4; block offset 6144B -> 16B aligned
        float4* szv = (float4*)sz;
        const float4* zv = (const float4*)(z + base * NDIM);
        szv[tid] = __ldcs(&zv[tid]);
        if (tid < 128) szv[256 + tid] = __ldcs(&zv[256 + tid]);
    } else {
        const int total = nrows * NDIM;
        for (int e = tid; e < total; e += THREADS)
            sz[e] = __ldcs(&z[base * NDIM + e]);
    }
    __syncthreads();

    if (tid < nrows) {
        int big = 0;
        #pragma unroll
        for (int i = 0; i < NDIM; i++) {
            const float v = sz[tid * NDIM + i];
            int idx = 0;
            // sorted per-dim edges: max{ j : v >= p[j] } == count over j>=1
            #pragma unroll
            for (int j = 1; j < JLEV; j++)
                idx += (v >= sp[j * NDIM + i]) ? 1 : 0;
            big |= idx << (3 * i);   // basis = 8^i
        }
        soff[tid] = (long long)big * CHAN;   // pre-scaled gather offset
        out_idx_f[base + tid] = (float)big;
    }
    __syncthreads();

    if (full) {
        // 16 lanes x float4 per row; 4096 float4 per block; each thread does
        // 16 vectors in 4 batches of 4 independent loads (MLP=4).
        // __ldcg: 64MB codebook never fits L1 -> skip L1 allocation.
        float4* dstb = (float4*)(out_q + base * (long long)CHAN);
        #pragma unroll
        for (int u0 = 0; u0 < 16; u0 += 4) {
            const float4* s[4];
            #pragma unroll
            for (int k = 0; k < 4; k++) {
                const int e = (u0 + k) * THREADS + tid;
                s[k] = (const float4*)(cb + soff[e >> 4]) + (e & 15);
            }
            float4 v0 = __ldcg(s[0]);
            float4 v1 = __ldcg(s[1]);
            float4 v2 = __ldcg(s[2]);
            float4 v3 = __ldcg(s[3]);
            __stcs(&dstb[(u0 + 0) * THREADS + tid], v0);
            __stcs(&dstb[(u0 + 1) * THREADS + tid], v1);
            __stcs(&dstb[(u0 + 2) * THREADS + tid], v2);
            __stcs(&dstb[(u0 + 3) * THREADS + tid], v3);
        }
    } else {
        const int totalv = nrows * (CHAN / 4);
        for (int e = tid; e < totalv; e += THREADS) {
            const int r = e >> 4;
            const int c = e & 15;
            const float4 v = __ldcg((const float4*)(cb + soff[r]) + c);
            __stcs((float4*)(out_q + (base + r) * (long long)CHAN) + c, v);
        }
    }
}

extern "C" void kernel_launch(void* const* d_in, const int* in_sizes, int n_in,
                              void* d_out, int out_size)
{
    const float* z    = (const float*)d_in[0];   // [B,6]
    const float* perc = (const float*)d_in[1];   // [8,6]
    const float* cb   = (const float*)d_in[2];   // [262144,64]
    const int B = in_sizes[0] / NDIM;

    const long long nq = (long long)B * CHAN;

    float* out_q     = (float*)d_out;
    float* out_idx_f = (float*)d_out + nq;   // confirmed layout: [B*64 | B]
    (void)out_size;

    const int blocks = (B + ROWS - 1) / ROWS;
    fsq_quantize_kernel<<<blocks, THREADS>>>(z, perc, cb, out_q, out_idx_f, B);
}